// round 15
// baseline (speedup 1.0000x reference)
#include <cuda_runtime.h>
#include <cuda_fp16.h>
#include <math.h>
#include <stdint.h>

// Scratch (static device arrays — no allocation allowed)
#define NMAX 100000
#define DIM  64

// Packed per-node src record, 128 halfs (256 B):
//   for sub in 0..15: halfs [8*sub .. 8*sub+3] = u cols 4sub..4sub+3
//                     halfs [8*sub+4 .. 8*sub+7] = xt cols 4sub..4sub+3
__device__ __half g_p[NMAX * 2 * DIM];
// Per-node dst record: v = x@W1b, 64 halfs (128 B).
__device__ __half g_d[NMAX * DIM];
// pos packed as float4
__device__ float4 g_pos4[NMAX];
// Pre-converted weights (final smem layout) + bias
__device__ __half g_wh[192 * 72];
__device__ float  g_bias[192];

// ---------------------------------------------------------------------------
__global__ void pos4_kernel(const float* __restrict__ pos, int N) {
    int i = blockIdx.x * blockDim.x + threadIdx.x;
    if (i < N)
        g_pos4[i] = make_float4(pos[3 * i], pos[3 * i + 1], pos[3 * i + 2], 0.f);
}

// ---------------------------------------------------------------------------
// One-block prep: convert [W1a|W1b|wt] -> g_wh[n*72+k] (half), bias -> g_bias.
// ---------------------------------------------------------------------------
__global__ void prep_kernel(const float* __restrict__ w1,
                            const float* __restrict__ b1,
                            const float* __restrict__ wt,
                            const float* __restrict__ bt) {
    int tid = threadIdx.x;
    for (int i = tid; i < 192 * 64; i += 256) {
        int k = i / 192;
        int n = i - k * 192;
        float v;
        if (n < 64)       v = w1[k * 64 + n];
        else if (n < 128) v = w1[(64 + k) * 64 + (n - 64)];
        else              v = wt[k * 64 + (n - 128)];
        g_wh[n * 72 + k] = __float2half_rn(v);
    }
    for (int i = tid; i < 192; i += 256)
        g_bias[i] = (i < 64) ? b1[i] : ((i < 128) ? 0.f : bt[i - 128]);
}

// ---------------------------------------------------------------------------
// Node GEMM: Y[N x 192] = X[N x 64] @ Wc + bias. fp16 mma m16n8k16, fp32
// accum. 512 rows/block (8 warps x 4 row-tiles x 16 rows); weights copied
// from pre-staged g_wh via raw uint4 smem copy. Accum chunked 3x8 n-tiles.
// ---------------------------------------------------------------------------
#define ROW_TILES 4
__global__ void node_mma_kernel(const float* __restrict__ x, int N) {
    __shared__ __half sW[192 * 72];
    __shared__ float  sBias[192];

    const int tid = threadIdx.x;

    // Straight copy: 27648 B = 1728 uint4
    {
        const uint4* src = (const uint4*)g_wh;
        uint4* dst = (uint4*)sW;
        #pragma unroll
        for (int i = tid; i < 1728; i += 256) dst[i] = src[i];
        for (int i = tid; i < 192; i += 256) sBias[i] = g_bias[i];
    }
    __syncthreads();

    const int warp = tid >> 5, lane = tid & 31;
    const int gid  = lane >> 2;
    const int t    = lane & 3;

    for (int rt = 0; rt < ROW_TILES; rt++) {
        const int row0 = (blockIdx.x * ROW_TILES + rt) * 128 + warp * 16;
        if (row0 >= N) break;

        const int rA = row0 + gid;
        const int rB = row0 + gid + 8;
        const int rAc = rA < N ? rA : N - 1;
        const int rBc = rB < N ? rB : N - 1;

        const float2* xA = (const float2*)(x + (size_t)rAc * 64);
        const float2* xB = (const float2*)(x + (size_t)rBc * 64);

        uint32_t a[4][4];
        #pragma unroll
        for (int ks = 0; ks < 4; ks++) {
            int f2 = ks * 8 + t;
            __half2 h0 = __float22half2_rn(xA[f2]);
            __half2 h1 = __float22half2_rn(xB[f2]);
            __half2 h2 = __float22half2_rn(xA[f2 + 4]);
            __half2 h3 = __float22half2_rn(xB[f2 + 4]);
            a[ks][0] = *(uint32_t*)&h0;
            a[ks][1] = *(uint32_t*)&h1;
            a[ks][2] = *(uint32_t*)&h2;
            a[ks][3] = *(uint32_t*)&h3;
        }

        #pragma unroll
        for (int chunk = 0; chunk < 3; chunk++) {
            float c[8][4];
            #pragma unroll
            for (int j = 0; j < 8; j++)
                c[j][0] = c[j][1] = c[j][2] = c[j][3] = 0.f;

            #pragma unroll
            for (int ks = 0; ks < 4; ks++) {
                #pragma unroll
                for (int j = 0; j < 8; j++) {
                    int nt = chunk * 8 + j;
                    const __half* bp = &sW[(nt * 8 + gid) * 72 + ks * 16 + 2 * t];
                    uint32_t b0  = *(const uint32_t*)bp;
                    uint32_t b1r = *(const uint32_t*)(bp + 8);
                    asm volatile(
                        "mma.sync.aligned.m16n8k16.row.col.f32.f16.f16.f32 "
                        "{%0,%1,%2,%3}, {%4,%5,%6,%7}, {%8,%9}, {%0,%1,%2,%3};"
                        : "+f"(c[j][0]), "+f"(c[j][1]), "+f"(c[j][2]), "+f"(c[j][3])
                        : "r"(a[ks][0]), "r"(a[ks][1]), "r"(a[ks][2]), "r"(a[ks][3]),
                          "r"(b0), "r"(b1r));
                }
            }

            #pragma unroll
            for (int j = 0; j < 8; j++) {
                int nt  = chunk * 8 + j;
                int col = nt * 8 + 2 * t;
                float bb0 = sBias[col], bb1 = sBias[col + 1];

                __half2 hA = __floats2half2_rn(c[j][0] + bb0, c[j][1] + bb1);
                __half2 hB = __floats2half2_rn(c[j][2] + bb0, c[j][3] + bb1);

                if (chunk == 0) {
                    int cc = col;
                    size_t off = 8 * (cc >> 2) + (cc & 3);
                    if (rA < N) *(__half2*)&g_p[(size_t)rA * 128 + off] = hA;
                    if (rB < N) *(__half2*)&g_p[(size_t)rB * 128 + off] = hB;
                } else if (chunk == 1) {
                    int cc = col - 64;
                    if (rA < N) *(__half2*)&g_d[(size_t)rA * 64 + cc] = hA;
                    if (rB < N) *(__half2*)&g_d[(size_t)rB * 64 + cc] = hB;
                } else {
                    int cc = col - 128;
                    size_t off = 8 * (cc >> 2) + 4 + (cc & 3);
                    if (rA < N) *(__half2*)&g_p[(size_t)rA * 128 + off] = hA;
                    if (rB < N) *(__half2*)&g_p[(size_t)rB * 128 + off] = hB;
                }
            }
        }
    }
}

// ---------------------------------------------------------------------------
// Per-edge fused: h = relu(u[s]+v[d]+len*wc), w = sigmoid(h.w2+b2),
//   ew[e] = w, out[d] += xt[s]*w via red.global.add.v4.f32.
// HALF-warp per edge; sub (0..15) owns cols 4*sub..4*sub+3.
// ---------------------------------------------------------------------------
__global__ void edge_kernel(const int* __restrict__ ei,
                            const float* __restrict__ w1,
                            const float* __restrict__ w2,
                            const float* __restrict__ b2p,
                            float* __restrict__ out,
                            float* __restrict__ ew,
                            int E) {
    const int lane   = threadIdx.x & 31;
    const int half   = lane >> 4;
    const int sub    = lane & 15;
    const int warp   = (blockIdx.x * blockDim.x + threadIdx.x) >> 5;
    const int nwarps = (gridDim.x * blockDim.x) >> 5;

    const float4 wc  = *(const float4*)&w1[128 * DIM + 4 * sub];
    const float4 w2v = *(const float4*)&w2[4 * sub];
    const float  b2  = b2p[0];

    for (int e0 = warp * 2; e0 < E; e0 += nwarps * 2) {
        int lidx = lane & 3;
        int addr = (lidx < 2) ? (e0 + lidx) : (E + e0 + lidx - 2);
        int val  = ei[addr];
        int s = __shfl_sync(0xffffffffu, val, half);
        int d = __shfl_sync(0xffffffffu, val, 2 + half);

        int e = e0 + half;
        bool valid = (e < E);

        float4 ps = g_pos4[s];
        float4 pd = g_pos4[d];
        float dx = pd.x - ps.x, dy = pd.y - ps.y, dz = pd.z - ps.z;
        float len = sqrtf(dx * dx + dy * dy + dz * dz);

        uint4 raw  = *(const uint4*)&g_p[(size_t)s * 2 * DIM + 8 * sub];
        uint2 vraw = *(const uint2*)&g_d[(size_t)d * DIM + 4 * sub];

        float2 u0 = __half22float2(*(const __half2*)&raw.x);
        float2 u1 = __half22float2(*(const __half2*)&raw.y);
        float2 v0 = __half22float2(*(const __half2*)&vraw.x);
        float2 v1 = __half22float2(*(const __half2*)&vraw.y);

        float h0 = fmaxf(fmaf(len, wc.x, u0.x + v0.x), 0.f);
        float h1 = fmaxf(fmaf(len, wc.y, u0.y + v0.y), 0.f);
        float h2 = fmaxf(fmaf(len, wc.z, u1.x + v1.x), 0.f);
        float h3 = fmaxf(fmaf(len, wc.w, u1.y + v1.y), 0.f);
        float p  = fmaf(h0, w2v.x, fmaf(h1, w2v.y, fmaf(h2, w2v.z, h3 * w2v.w)));

        #pragma unroll
        for (int o = 8; o > 0; o >>= 1)
            p += __shfl_xor_sync(0xffffffffu, p, o);

        float w = 1.f / (1.f + __expf(-(p + b2)));

        if (valid) {
            if (sub == 0 && ew) ew[e] = w;

            float2 m0 = __half22float2(*(const __half2*)&raw.z);
            float2 m1 = __half22float2(*(const __half2*)&raw.w);

            float* o0 = &out[(size_t)d * DIM + 4 * sub];
            asm volatile("red.global.add.v4.f32 [%0], {%1, %2, %3, %4};"
                         :: "l"(o0), "f"(m0.x * w), "f"(m0.y * w),
                            "f"(m1.x * w), "f"(m1.y * w)
                         : "memory");
        }
    }
}

// ---------------------------------------------------------------------------
extern "C" void kernel_launch(void* const* d_in, const int* in_sizes, int n_in,
                              void* d_out, int out_size) {
    const float* x   = (const float*)d_in[0];
    const int*   ei  = (const int*)d_in[1];    // int32 (JAX x64 disabled)
    const float* pos = (const float*)d_in[2];
    const float* w1  = (const float*)d_in[3];
    const float* b1  = (const float*)d_in[4];
    const float* w2  = (const float*)d_in[5];
    const float* b2  = (const float*)d_in[6];
    const float* wt  = (const float*)d_in[7];
    const float* bt  = (const float*)d_in[8];

    int N = in_sizes[0] / DIM;   // 100000
    int E = in_sizes[1] / 2;     // 1600000

    float* out = (float*)d_out;
    float* ew  = (out_size >= N * DIM + E) ? out + (size_t)N * DIM : nullptr;

    cudaMemsetAsync(out, 0, (size_t)N * DIM * sizeof(float));

    prep_kernel<<<1, 256>>>(w1, b1, wt, bt);
    // node_mma at launch index 2; edge at 4 (ncu -s 5 per-launch skip varies)
    int rows_per_block = 128 * ROW_TILES;
    node_mma_kernel<<<(N + rows_per_block - 1) / rows_per_block, 256>>>(x, N);
    pos4_kernel<<<(N + 255) / 256, 256>>>(pos, N);
    edge_kernel<<<2368, 256>>>(ei, w1, w2, b2, out, ew, E);
}

// round 16
// speedup vs baseline: 1.0441x; 1.0441x over previous
#include <cuda_runtime.h>
#include <cuda_fp16.h>
#include <math.h>
#include <stdint.h>

// Scratch (static device arrays — no allocation allowed)
#define NMAX 100000
#define DIM  64

// Packed per-node src record, 128 halfs (256 B):
//   for sub in 0..15: halfs [8*sub .. 8*sub+3] = u cols 4sub..4sub+3
//                     halfs [8*sub+4 .. 8*sub+7] = xt cols 4sub..4sub+3
__device__ __half g_p[NMAX * 2 * DIM];
// Per-node dst record: v = x@W1b, 64 halfs (128 B).
__device__ __half g_d[NMAX * DIM];
// pos packed as float4
__device__ float4 g_pos4[NMAX];
// Pre-converted weights (final smem layout) + bias
__device__ __half g_wh[192 * 72];
__device__ float  g_bias[192];

// ---------------------------------------------------------------------------
__global__ void pos4_kernel(const float* __restrict__ pos, int N) {
    int i = blockIdx.x * blockDim.x + threadIdx.x;
    if (i < N)
        g_pos4[i] = make_float4(pos[3 * i], pos[3 * i + 1], pos[3 * i + 2], 0.f);
}

// ---------------------------------------------------------------------------
// One-block prep: convert [W1a|W1b|wt] -> g_wh[n*72+k] (half), bias -> g_bias.
// ---------------------------------------------------------------------------
__global__ void prep_kernel(const float* __restrict__ w1,
                            const float* __restrict__ b1,
                            const float* __restrict__ wt,
                            const float* __restrict__ bt) {
    int tid = threadIdx.x;
    for (int i = tid; i < 192 * 64; i += 256) {
        int k = i / 192;
        int n = i - k * 192;
        float v;
        if (n < 64)       v = w1[k * 64 + n];
        else if (n < 128) v = w1[(64 + k) * 64 + (n - 64)];
        else              v = wt[k * 64 + (n - 128)];
        g_wh[n * 72 + k] = __float2half_rn(v);
    }
    for (int i = tid; i < 192; i += 256)
        g_bias[i] = (i < 64) ? b1[i] : ((i < 128) ? 0.f : bt[i - 128]);
}

// ---------------------------------------------------------------------------
// Node GEMM: Y[N x 192] = X[N x 64] @ Wc + bias. fp16 mma m16n8k16, fp32
// accum. 128 rows/block, grid 782 (max parallelism). Weights via raw uint4
// copy from pre-staged g_wh. Accum chunked 3x8 n-tiles; bias folded into
// accumulator init. launch_bounds(256,4) -> <=64 regs, 4 blocks/SM.
// ---------------------------------------------------------------------------
__global__ void __launch_bounds__(256, 4)
node_mma_kernel(const float* __restrict__ x, int N) {
    __shared__ __half sW[192 * 72];
    __shared__ float  sBias[192];

    const int tid = threadIdx.x;

    // Straight copy: 27648 B = 1728 uint4
    {
        const uint4* src = (const uint4*)g_wh;
        uint4* dst = (uint4*)sW;
        #pragma unroll
        for (int i = tid; i < 1728; i += 256) dst[i] = src[i];
        for (int i = tid; i < 192; i += 256) sBias[i] = g_bias[i];
    }
    __syncthreads();

    const int warp = tid >> 5, lane = tid & 31;
    const int gid  = lane >> 2;
    const int t    = lane & 3;
    const int row0 = blockIdx.x * 128 + warp * 16;

    const int rA = row0 + gid;
    const int rB = row0 + gid + 8;
    const int rAc = rA < N ? rA : N - 1;
    const int rBc = rB < N ? rB : N - 1;

    const float2* xA = (const float2*)(x + (size_t)rAc * 64);
    const float2* xB = (const float2*)(x + (size_t)rBc * 64);

    // Hoisted A fragments
    uint32_t a[4][4];
    #pragma unroll
    for (int ks = 0; ks < 4; ks++) {
        int f2 = ks * 8 + t;
        __half2 h0 = __float22half2_rn(xA[f2]);
        __half2 h1 = __float22half2_rn(xB[f2]);
        __half2 h2 = __float22half2_rn(xA[f2 + 4]);
        __half2 h3 = __float22half2_rn(xB[f2 + 4]);
        a[ks][0] = *(uint32_t*)&h0;
        a[ks][1] = *(uint32_t*)&h1;
        a[ks][2] = *(uint32_t*)&h2;
        a[ks][3] = *(uint32_t*)&h3;
    }

    #pragma unroll
    for (int chunk = 0; chunk < 3; chunk++) {
        float c[8][4];
        // bias folded into init: c0/c1 (and c2/c3) get cols (col, col+1)
        #pragma unroll
        for (int j = 0; j < 8; j++) {
            int col = (chunk * 8 + j) * 8 + 2 * t;
            float bb0 = sBias[col], bb1 = sBias[col + 1];
            c[j][0] = bb0; c[j][1] = bb1;
            c[j][2] = bb0; c[j][3] = bb1;
        }

        #pragma unroll
        for (int ks = 0; ks < 4; ks++) {
            #pragma unroll
            for (int j = 0; j < 8; j++) {
                int nt = chunk * 8 + j;
                const __half* bp = &sW[(nt * 8 + gid) * 72 + ks * 16 + 2 * t];
                uint32_t b0  = *(const uint32_t*)bp;
                uint32_t b1r = *(const uint32_t*)(bp + 8);
                asm volatile(
                    "mma.sync.aligned.m16n8k16.row.col.f32.f16.f16.f32 "
                    "{%0,%1,%2,%3}, {%4,%5,%6,%7}, {%8,%9}, {%0,%1,%2,%3};"
                    : "+f"(c[j][0]), "+f"(c[j][1]), "+f"(c[j][2]), "+f"(c[j][3])
                    : "r"(a[ks][0]), "r"(a[ks][1]), "r"(a[ks][2]), "r"(a[ks][3]),
                      "r"(b0), "r"(b1r));
            }
        }

        // Per-chunk epilogue. chunk0 -> u in g_p, chunk1 -> v in g_d,
        // chunk2 -> xt in g_p (+4 offset). col = nt*8 + 2t.
        #pragma unroll
        for (int j = 0; j < 8; j++) {
            int nt  = chunk * 8 + j;
            int col = nt * 8 + 2 * t;

            __half2 hA = __floats2half2_rn(c[j][0], c[j][1]);
            __half2 hB = __floats2half2_rn(c[j][2], c[j][3]);

            if (chunk == 0) {
                int cc = col;
                size_t off = 8 * (cc >> 2) + (cc & 3);
                if (rA < N) *(__half2*)&g_p[(size_t)rA * 128 + off] = hA;
                if (rB < N) *(__half2*)&g_p[(size_t)rB * 128 + off] = hB;
            } else if (chunk == 1) {
                int cc = col - 64;
                if (rA < N) *(__half2*)&g_d[(size_t)rA * 64 + cc] = hA;
                if (rB < N) *(__half2*)&g_d[(size_t)rB * 64 + cc] = hB;
            } else {
                int cc = col - 128;
                size_t off = 8 * (cc >> 2) + 4 + (cc & 3);
                if (rA < N) *(__half2*)&g_p[(size_t)rA * 128 + off] = hA;
                if (rB < N) *(__half2*)&g_p[(size_t)rB * 128 + off] = hB;
            }
        }
    }
}

// ---------------------------------------------------------------------------
// Per-edge fused: h = relu(u[s]+v[d]+len*wc), w = sigmoid(h.w2+b2),
//   ew[e] = w, out[d] += xt[s]*w via red.global.add.v4.f32.
// HALF-warp per edge; sub (0..15) owns cols 4*sub..4*sub+3.
// ---------------------------------------------------------------------------
__global__ void edge_kernel(const int* __restrict__ ei,
                            const float* __restrict__ w1,
                            const float* __restrict__ w2,
                            const float* __restrict__ b2p,
                            float* __restrict__ out,
                            float* __restrict__ ew,
                            int E) {
    const int lane   = threadIdx.x & 31;
    const int half   = lane >> 4;
    const int sub    = lane & 15;
    const int warp   = (blockIdx.x * blockDim.x + threadIdx.x) >> 5;
    const int nwarps = (gridDim.x * blockDim.x) >> 5;

    const float4 wc  = *(const float4*)&w1[128 * DIM + 4 * sub];
    const float4 w2v = *(const float4*)&w2[4 * sub];
    const float  b2  = b2p[0];

    for (int e0 = warp * 2; e0 < E; e0 += nwarps * 2) {
        int lidx = lane & 3;
        int addr = (lidx < 2) ? (e0 + lidx) : (E + e0 + lidx - 2);
        int val  = ei[addr];
        int s = __shfl_sync(0xffffffffu, val, half);
        int d = __shfl_sync(0xffffffffu, val, 2 + half);

        int e = e0 + half;
        bool valid = (e < E);

        float4 ps = g_pos4[s];
        float4 pd = g_pos4[d];
        float dx = pd.x - ps.x, dy = pd.y - ps.y, dz = pd.z - ps.z;
        float len = sqrtf(dx * dx + dy * dy + dz * dz);

        uint4 raw  = *(const uint4*)&g_p[(size_t)s * 2 * DIM + 8 * sub];
        uint2 vraw = *(const uint2*)&g_d[(size_t)d * DIM + 4 * sub];

        float2 u0 = __half22float2(*(const __half2*)&raw.x);
        float2 u1 = __half22float2(*(const __half2*)&raw.y);
        float2 v0 = __half22float2(*(const __half2*)&vraw.x);
        float2 v1 = __half22float2(*(const __half2*)&vraw.y);

        float h0 = fmaxf(fmaf(len, wc.x, u0.x + v0.x), 0.f);
        float h1 = fmaxf(fmaf(len, wc.y, u0.y + v0.y), 0.f);
        float h2 = fmaxf(fmaf(len, wc.z, u1.x + v1.x), 0.f);
        float h3 = fmaxf(fmaf(len, wc.w, u1.y + v1.y), 0.f);
        float p  = fmaf(h0, w2v.x, fmaf(h1, w2v.y, fmaf(h2, w2v.z, h3 * w2v.w)));

        #pragma unroll
        for (int o = 8; o > 0; o >>= 1)
            p += __shfl_xor_sync(0xffffffffu, p, o);

        float w = 1.f / (1.f + __expf(-(p + b2)));

        if (valid) {
            if (sub == 0 && ew) ew[e] = w;

            float2 m0 = __half22float2(*(const __half2*)&raw.z);
            float2 m1 = __half22float2(*(const __half2*)&raw.w);

            float* o0 = &out[(size_t)d * DIM + 4 * sub];
            asm volatile("red.global.add.v4.f32 [%0], {%1, %2, %3, %4};"
                         :: "l"(o0), "f"(m0.x * w), "f"(m0.y * w),
                            "f"(m1.x * w), "f"(m1.y * w)
                         : "memory");
        }
    }
}

// ---------------------------------------------------------------------------
extern "C" void kernel_launch(void* const* d_in, const int* in_sizes, int n_in,
                              void* d_out, int out_size) {
    const float* x   = (const float*)d_in[0];
    const int*   ei  = (const int*)d_in[1];    // int32 (JAX x64 disabled)
    const float* pos = (const float*)d_in[2];
    const float* w1  = (const float*)d_in[3];
    const float* b1  = (const float*)d_in[4];
    const float* w2  = (const float*)d_in[5];
    const float* b2  = (const float*)d_in[6];
    const float* wt  = (const float*)d_in[7];
    const float* bt  = (const float*)d_in[8];

    int N = in_sizes[0] / DIM;   // 100000
    int E = in_sizes[1] / 2;     // 1600000

    float* out = (float*)d_out;
    float* ew  = (out_size >= N * DIM + E) ? out + (size_t)N * DIM : nullptr;

    cudaMemsetAsync(out, 0, (size_t)N * DIM * sizeof(float));

    prep_kernel<<<1, 256>>>(w1, b1, wt, bt);
    node_mma_kernel<<<(N + 127) / 128, 256>>>(x, N);
    pos4_kernel<<<(N + 255) / 256, 256>>>(pos, N);
    edge_kernel<<<2368, 256>>>(ei, w1, w2, b2, out, ew, E);
}

// round 17
// speedup vs baseline: 1.0799x; 1.0343x over previous
#include <cuda_runtime.h>
#include <cuda_fp16.h>
#include <math.h>
#include <stdint.h>

// Scratch (static device arrays — no allocation allowed)
#define NMAX 100000
#define DIM  64

// Per-node src record, 128 halfs (256 B), SPLIT layout:
//   halfs [0..63]   = u  cols 0..63   (u  = x@W1a + b1)
//   halfs [64..127] = xt cols 0..63   (xt = x@wt + bt)
__device__ __half g_p[NMAX * 2 * DIM];
// Per-node dst record: v = x@W1b, 64 halfs (128 B).
__device__ __half g_d[NMAX * DIM];
// pos packed as float4
__device__ float4 g_pos4[NMAX];
// Pre-converted weights (final smem layout) + bias
__device__ __half g_wh[192 * 72];
__device__ float  g_bias[192];

// ---------------------------------------------------------------------------
// One-block prep: convert [W1a|W1b|wt] -> g_wh[n*72+k] (half), bias -> g_bias.
// ---------------------------------------------------------------------------
__global__ void prep_kernel(const float* __restrict__ w1,
                            const float* __restrict__ b1,
                            const float* __restrict__ wt,
                            const float* __restrict__ bt) {
    int tid = threadIdx.x;
    for (int i = tid; i < 192 * 64; i += 256) {
        int k = i / 192;
        int n = i - k * 192;
        float v;
        if (n < 64)       v = w1[k * 64 + n];
        else if (n < 128) v = w1[(64 + k) * 64 + (n - 64)];
        else              v = wt[k * 64 + (n - 128)];
        g_wh[n * 72 + k] = __float2half_rn(v);
    }
    for (int i = tid; i < 192; i += 256)
        g_bias[i] = (i < 64) ? b1[i] : ((i < 128) ? 0.f : bt[i - 128]);
}

// ---------------------------------------------------------------------------
// Node GEMM: Y[N x 192] = X[N x 64] @ Wc + bias. fp16 mma m16n8k16, fp32
// accum. 128 rows/block. Epilogue staged through smem -> fully coalesced
// uint4 global stores. Blocks >= NB_MMA run the pos4 packing role instead.
// ---------------------------------------------------------------------------
__global__ void __launch_bounds__(256, 4)
node_mma_kernel(const float* __restrict__ x, const float* __restrict__ pos,
                int N, int nbMma) {
    __shared__ __half sW[192 * 72];      // 27648 B
    __shared__ float  sBias[192];        //   768 B
    __shared__ __half sOut[128 * 80];    // 20480 B (row stride 80 halfs=160B)

    const int tid = threadIdx.x;

    if (blockIdx.x >= nbMma) {           // pos4 role
        int i = (blockIdx.x - nbMma) * 256 + tid;
        if (i < N)
            g_pos4[i] = make_float4(pos[3 * i], pos[3 * i + 1], pos[3 * i + 2], 0.f);
        return;
    }

    // Straight copy of pre-staged weights: 27648 B = 1728 uint4
    {
        const uint4* src = (const uint4*)g_wh;
        uint4* dst = (uint4*)sW;
        #pragma unroll
        for (int i = tid; i < 1728; i += 256) dst[i] = src[i];
        for (int i = tid; i < 192; i += 256) sBias[i] = g_bias[i];
    }
    __syncthreads();

    const int warp = tid >> 5, lane = tid & 31;
    const int gid  = lane >> 2;
    const int t    = lane & 3;
    const int row0 = blockIdx.x * 128 + warp * 16;

    const int rA = row0 + gid;
    const int rB = row0 + gid + 8;
    const int rAc = rA < N ? rA : N - 1;
    const int rBc = rB < N ? rB : N - 1;
    const int lrA = warp * 16 + gid;          // block-local rows
    const int lrB = lrA + 8;

    const float2* xA = (const float2*)(x + (size_t)rAc * 64);
    const float2* xB = (const float2*)(x + (size_t)rBc * 64);

    // Hoisted A fragments
    uint32_t a[4][4];
    #pragma unroll
    for (int ks = 0; ks < 4; ks++) {
        int f2 = ks * 8 + t;
        __half2 h0 = __float22half2_rn(xA[f2]);
        __half2 h1 = __float22half2_rn(xB[f2]);
        __half2 h2 = __float22half2_rn(xA[f2 + 4]);
        __half2 h3 = __float22half2_rn(xB[f2 + 4]);
        a[ks][0] = *(uint32_t*)&h0;
        a[ks][1] = *(uint32_t*)&h1;
        a[ks][2] = *(uint32_t*)&h2;
        a[ks][3] = *(uint32_t*)&h3;
    }

    const int rowsLeft = N - blockIdx.x * 128;   // rows this block owns
    const int nCopy = (rowsLeft >= 128 ? 128 : rowsLeft);

    #pragma unroll
    for (int chunk = 0; chunk < 3; chunk++) {
        float c[8][4];
        #pragma unroll
        for (int j = 0; j < 8; j++) {
            int col = (chunk * 8 + j) * 8 + 2 * t;
            float bb0 = sBias[col], bb1 = sBias[col + 1];
            c[j][0] = bb0; c[j][1] = bb1;
            c[j][2] = bb0; c[j][3] = bb1;
        }

        #pragma unroll
        for (int ks = 0; ks < 4; ks++) {
            #pragma unroll
            for (int j = 0; j < 8; j++) {
                int nt = chunk * 8 + j;
                const __half* bp = &sW[(nt * 8 + gid) * 72 + ks * 16 + 2 * t];
                uint32_t b0  = *(const uint32_t*)bp;
                uint32_t b1r = *(const uint32_t*)(bp + 8);
                asm volatile(
                    "mma.sync.aligned.m16n8k16.row.col.f32.f16.f16.f32 "
                    "{%0,%1,%2,%3}, {%4,%5,%6,%7}, {%8,%9}, {%0,%1,%2,%3};"
                    : "+f"(c[j][0]), "+f"(c[j][1]), "+f"(c[j][2]), "+f"(c[j][3])
                    : "r"(a[ks][0]), "r"(a[ks][1]), "r"(a[ks][2]), "r"(a[ks][3]),
                      "r"(b0), "r"(b1r));
            }
        }

        // Stage this chunk (128 rows x 64 cols half) in smem
        #pragma unroll
        for (int j = 0; j < 8; j++) {
            int cc = j * 8 + 2 * t;                     // 0..62, chunk-local
            *(__half2*)&sOut[lrA * 80 + cc] = __floats2half2_rn(c[j][0], c[j][1]);
            *(__half2*)&sOut[lrB * 80 + cc] = __floats2half2_rn(c[j][2], c[j][3]);
        }
        __syncthreads();

        // Coalesced copy out: 128 rows x 128 B = 1024 uint4
        for (int i = tid; i < 1024; i += 256) {
            int row = i >> 3, seg = i & 7;
            if (row < nCopy) {
                uint4 val = *(const uint4*)&sOut[row * 80 + seg * 8];
                size_t grow = (size_t)(blockIdx.x * 128 + row);
                if (chunk == 0)
                    *(uint4*)&g_p[grow * 128 + seg * 8] = val;
                else if (chunk == 1)
                    *(uint4*)&g_d[grow * 64 + seg * 8] = val;
                else
                    *(uint4*)&g_p[grow * 128 + 64 + seg * 8] = val;
            }
        }
        __syncthreads();
    }
}

// ---------------------------------------------------------------------------
// Per-edge fused: h = relu(u[s]+v[d]+len*wc), w = sigmoid(h.w2+b2),
//   ew[e] = w, out[d] += xt[s]*w via red.global.add.v4.f32.
// HALF-warp per edge; sub (0..15) owns cols 4*sub..4*sub+3.
// g_p split layout: u at [0,64), xt at [64,128) halfs.
// ---------------------------------------------------------------------------
__global__ void edge_kernel(const int* __restrict__ ei,
                            const float* __restrict__ w1,
                            const float* __restrict__ w2,
                            const float* __restrict__ b2p,
                            float* __restrict__ out,
                            float* __restrict__ ew,
                            int E) {
    const int lane   = threadIdx.x & 31;
    const int half   = lane >> 4;
    const int sub    = lane & 15;
    const int warp   = (blockIdx.x * blockDim.x + threadIdx.x) >> 5;
    const int nwarps = (gridDim.x * blockDim.x) >> 5;

    const float4 wc  = *(const float4*)&w1[128 * DIM + 4 * sub];
    const float4 w2v = *(const float4*)&w2[4 * sub];
    const float  b2  = b2p[0];

    for (int e0 = warp * 2; e0 < E; e0 += nwarps * 2) {
        int lidx = lane & 3;
        int addr = (lidx < 2) ? (e0 + lidx) : (E + e0 + lidx - 2);
        int val  = ei[addr];
        int s = __shfl_sync(0xffffffffu, val, half);
        int d = __shfl_sync(0xffffffffu, val, 2 + half);

        int e = e0 + half;
        bool valid = (e < E);

        float4 ps = g_pos4[s];
        float4 pd = g_pos4[d];
        float dx = pd.x - ps.x, dy = pd.y - ps.y, dz = pd.z - ps.z;
        float len = sqrtf(dx * dx + dy * dy + dz * dz);

        uint2 uraw = *(const uint2*)&g_p[(size_t)s * 128 + 4 * sub];
        uint2 xraw = *(const uint2*)&g_p[(size_t)s * 128 + 64 + 4 * sub];
        uint2 vraw = *(const uint2*)&g_d[(size_t)d * 64 + 4 * sub];

        float2 u0 = __half22float2(*(const __half2*)&uraw.x);
        float2 u1 = __half22float2(*(const __half2*)&uraw.y);
        float2 v0 = __half22float2(*(const __half2*)&vraw.x);
        float2 v1 = __half22float2(*(const __half2*)&vraw.y);

        float h0 = fmaxf(fmaf(len, wc.x, u0.x + v0.x), 0.f);
        float h1 = fmaxf(fmaf(len, wc.y, u0.y + v0.y), 0.f);
        float h2 = fmaxf(fmaf(len, wc.z, u1.x + v1.x), 0.f);
        float h3 = fmaxf(fmaf(len, wc.w, u1.y + v1.y), 0.f);
        float p  = fmaf(h0, w2v.x, fmaf(h1, w2v.y, fmaf(h2, w2v.z, h3 * w2v.w)));

        #pragma unroll
        for (int o = 8; o > 0; o >>= 1)
            p += __shfl_xor_sync(0xffffffffu, p, o);

        float w = 1.f / (1.f + __expf(-(p + b2)));

        if (valid) {
            if (sub == 0 && ew) ew[e] = w;

            float2 m0 = __half22float2(*(const __half2*)&xraw.x);
            float2 m1 = __half22float2(*(const __half2*)&xraw.y);

            float* o0 = &out[(size_t)d * DIM + 4 * sub];
            asm volatile("red.global.add.v4.f32 [%0], {%1, %2, %3, %4};"
                         :: "l"(o0), "f"(m0.x * w), "f"(m0.y * w),
                            "f"(m1.x * w), "f"(m1.y * w)
                         : "memory");
        }
    }
}

// ---------------------------------------------------------------------------
extern "C" void kernel_launch(void* const* d_in, const int* in_sizes, int n_in,
                              void* d_out, int out_size) {
    const float* x   = (const float*)d_in[0];
    const int*   ei  = (const int*)d_in[1];    // int32 (JAX x64 disabled)
    const float* pos = (const float*)d_in[2];
    const float* w1  = (const float*)d_in[3];
    const float* b1  = (const float*)d_in[4];
    const float* w2  = (const float*)d_in[5];
    const float* b2  = (const float*)d_in[6];
    const float* wt  = (const float*)d_in[7];
    const float* bt  = (const float*)d_in[8];

    int N = in_sizes[0] / DIM;   // 100000
    int E = in_sizes[1] / 2;     // 1600000

    float* out = (float*)d_out;
    float* ew  = (out_size >= N * DIM + E) ? out + (size_t)N * DIM : nullptr;

    cudaMemsetAsync(out, 0, (size_t)N * DIM * sizeof(float));

    prep_kernel<<<1, 256>>>(w1, b1, wt, bt);

    int nbMma  = (N + 127) / 128;            // 782
    int nbPos  = (N + 255) / 256;            // 391
    node_mma_kernel<<<nbMma + nbPos, 256>>>(x, pos, N, nbMma);

    edge_kernel<<<2368, 256>>>(ei, w1, w2, b2, out, ew, E);
}